// round 3
// baseline (speedup 1.0000x reference)
#include <cuda_runtime.h>

#define N_NODES 100000
#define N_EDGES 640000
#define D 128

// ---------------- scratch (device globals; no dynamic allocation) ----------
__device__ float g_conv[N_NODES * D];   // W2-projection, send-scaled
__device__ float g_degs[N_NODES];       // send degree -> rsqrt factor
__device__ float g_degr[N_NODES];       // recv degree -> rsqrt factor
__device__ float g_gvec[D];             // globals @ W3 + b3
__device__ float g_an[D];               // sum over nodes of h

// ---------------- init ------------------------------------------------------
__global__ void zero_kernel() {
    int i = blockIdx.x * blockDim.x + threadIdx.x;
    if (i < N_NODES) { g_degs[i] = 0.f; g_degr[i] = 0.f; }
    if (i < D) g_an[i] = 0.f;
}

__global__ void degree_kernel(const int* __restrict__ senders,
                              const int* __restrict__ receivers) {
    int e = blockIdx.x * blockDim.x + threadIdx.x;
    if (e < N_EDGES) {
        atomicAdd(&g_degs[senders[e]], 1.f);
        atomicAdd(&g_degr[receivers[e]], 1.f);
    }
}

__global__ void rs_kernel() {
    int i = blockIdx.x * blockDim.x + threadIdx.x;
    if (i < N_NODES) {
        g_degs[i] = rsqrtf(fmaxf(g_degs[i], 1.f));
        g_degr[i] = rsqrtf(fmaxf(g_degr[i], 1.f));
    }
}

// ---------------- globals -> node broadcast vector (globals @ W3 + b3) -----
__global__ void gvec_kernel(const float* __restrict__ g,
                            const float* __restrict__ W3,
                            const float* __restrict__ b3) {
    __shared__ float sg[D];
    int c = threadIdx.x;           // 128 threads
    sg[c] = g[c];
    __syncthreads();
    float acc = b3[c];
#pragma unroll 8
    for (int k = 0; k < D; k++) acc += sg[k] * W3[k * D + c];
    g_gvec[c] = acc;
}

// ---------------- fused dual GEMM: h1 = nodes@W1+b1+gvec ; conv = (nodes@W2+b2)*rs_send
#define BM 64
#define GEMM_SMEM ((2 * D * D + BM * D) * (int)sizeof(float))  // 160 KB

__global__ __launch_bounds__(256, 1)
void gemm_kernel(const float* __restrict__ nodes,
                 const float* __restrict__ W1, const float* __restrict__ b1,
                 const float* __restrict__ W2, const float* __restrict__ b2,
                 float* __restrict__ out) {
    extern __shared__ float smem[];
    float* sW1 = smem;             // 128x128
    float* sW2 = smem + D * D;     // 128x128
    float* sA  = smem + 2 * D * D; // BM x 128

    int tid  = threadIdx.x;        // 256 threads
    int row0 = blockIdx.x * BM;

    // load both weight matrices (float4)
    for (int i = tid; i < D * D / 4; i += 256) {
        ((float4*)sW1)[i] = ((const float4*)W1)[i];
        ((float4*)sW2)[i] = ((const float4*)W2)[i];
    }
    // load A tile
    for (int i = tid; i < BM * D / 4; i += 256) {
        int r  = i / (D / 4);
        int gr = row0 + r;
        ((float4*)sA)[i] = (gr < N_NODES)
            ? ((const float4*)nodes)[gr * (D / 4) + (i % (D / 4))]
            : make_float4(0.f, 0.f, 0.f, 0.f);
    }
    __syncthreads();

    int cg = tid & 31;             // 32 column groups of 4
    int rg = tid >> 5;             // 8 row groups of 8
    int c0 = cg * 4;
    int r0 = rg * 8;

    float acc1[8][4] = {}, acc2[8][4] = {};

    for (int k = 0; k < D; k += 4) {
        float w1s[4][4], w2s[4][4];
#pragma unroll
        for (int dk = 0; dk < 4; dk++) {
            float4 t1 = *(const float4*)&sW1[(k + dk) * D + c0];
            float4 t2 = *(const float4*)&sW2[(k + dk) * D + c0];
            w1s[dk][0] = t1.x; w1s[dk][1] = t1.y; w1s[dk][2] = t1.z; w1s[dk][3] = t1.w;
            w2s[dk][0] = t2.x; w2s[dk][1] = t2.y; w2s[dk][2] = t2.z; w2s[dk][3] = t2.w;
        }
#pragma unroll
        for (int r = 0; r < 8; r++) {
            float4 av = *(const float4*)&sA[(r0 + r) * D + k];  // warp-uniform broadcast
            float a[4] = {av.x, av.y, av.z, av.w};
#pragma unroll
            for (int dk = 0; dk < 4; dk++)
#pragma unroll
                for (int c = 0; c < 4; c++) {
                    acc1[r][c] += a[dk] * w1s[dk][c];
                    acc2[r][c] += a[dk] * w2s[dk][c];
                }
        }
    }

    // epilogue
    float4 bv1 = *(const float4*)&b1[c0];
    float4 bv2 = *(const float4*)&b2[c0];
    float4 gv  = *(const float4*)&g_gvec[c0];
#pragma unroll
    for (int r = 0; r < 8; r++) {
        int gr = row0 + r0 + r;
        if (gr < N_NODES) {
            float rsv = g_degs[gr];  // rsqrt(max(send_deg,1))
            float4 o, cvt;
            o.x = acc1[r][0] + bv1.x + gv.x;
            o.y = acc1[r][1] + bv1.y + gv.y;
            o.z = acc1[r][2] + bv1.z + gv.z;
            o.w = acc1[r][3] + bv1.w + gv.w;
            cvt.x = (acc2[r][0] + bv2.x) * rsv;
            cvt.y = (acc2[r][1] + bv2.y) * rsv;
            cvt.z = (acc2[r][2] + bv2.z) * rsv;
            cvt.w = (acc2[r][3] + bv2.w) * rsv;
            *(float4*)&out[gr * D + c0]    = o;
            *(float4*)&g_conv[gr * D + c0] = cvt;
        }
    }
}

// ---------------- edge scatter: out[r] += conv[s] * rsqrt(recv_deg[r]) -----
__global__ void edge_kernel(const int* __restrict__ senders,
                            const int* __restrict__ receivers,
                            float* __restrict__ out) {
    int t    = blockIdx.x * blockDim.x + threadIdx.x;
    int e    = t >> 5;
    int lane = t & 31;
    if (e >= N_EDGES) return;
    int s = __ldg(&senders[e]);
    int r = __ldg(&receivers[e]);
    float rr = g_degr[r];            // rsqrt(max(recv_deg,1))
    float4 v = *(const float4*)&g_conv[s * D + lane * 4];
    float* dst = &out[r * D + lane * 4];
    asm volatile("red.global.add.v4.f32 [%0], {%1,%2,%3,%4};"
                 :: "l"(dst), "f"(v.x * rr), "f"(v.y * rr), "f"(v.z * rr), "f"(v.w * rr)
                 : "memory");
}

// ---------------- finalize: h = relu(h1+gvec+agg) + nodes ; an = sum(h) ----
#define RPB 64
__global__ void finalize_kernel(const float* __restrict__ nodes,
                                float* __restrict__ out) {
    int c    = threadIdx.x;          // 128 threads = 1 column each
    int row0 = blockIdx.x * RPB;
    float s = 0.f;
#pragma unroll 4
    for (int r = 0; r < RPB; r++) {
        int gr = row0 + r;
        if (gr >= N_NODES) break;
        int idx = gr * D + c;
        float v = fmaxf(out[idx], 0.f) + nodes[idx];
        out[idx] = v;
        s += v;
    }
    atomicAdd(&g_an[c], s);
}

// ---------------- global update: g_new = g + relu([an; g] @ Wg + bg) -------
__global__ void gnew_kernel(const float* __restrict__ g,
                            const float* __restrict__ Wg,
                            const float* __restrict__ bg,
                            float* __restrict__ out2) {
    __shared__ float sv[2 * D];
    int c = threadIdx.x;             // 128 threads
    sv[c]     = g_an[c];
    sv[D + c] = g[c];
    __syncthreads();
    float acc = bg[c];
#pragma unroll 8
    for (int k = 0; k < 2 * D; k++) acc += sv[k] * Wg[k * D + c];
    out2[c] = g[c] + fmaxf(acc, 0.f);
}

// ---------------- launch ----------------------------------------------------
extern "C" void kernel_launch(void* const* d_in, const int* in_sizes, int n_in,
                              void* d_out, int out_size) {
    const float* nodes    = (const float*)d_in[0];
    const float* globals_ = (const float*)d_in[1];
    const int*   senders   = (const int*)d_in[2];
    const int*   receivers = (const int*)d_in[3];
    const float* W1w = (const float*)d_in[4];
    const float* W1b = (const float*)d_in[5];
    const float* W2w = (const float*)d_in[6];
    const float* W2b = (const float*)d_in[7];
    const float* W3w = (const float*)d_in[8];
    const float* W3b = (const float*)d_in[9];
    const float* Wgw = (const float*)d_in[10];
    const float* Wgb = (const float*)d_in[11];
    float* out = (float*)d_out;

    cudaFuncSetAttribute(gemm_kernel, cudaFuncAttributeMaxDynamicSharedMemorySize,
                         GEMM_SMEM);

    zero_kernel<<<(N_NODES + 255) / 256, 256>>>();
    degree_kernel<<<(N_EDGES + 255) / 256, 256>>>(senders, receivers);
    rs_kernel<<<(N_NODES + 255) / 256, 256>>>();
    gvec_kernel<<<1, 128>>>(globals_, W3w, W3b);
    gemm_kernel<<<(N_NODES + BM - 1) / BM, 256, GEMM_SMEM>>>(nodes, W1w, W1b, W2w, W2b, out);
    edge_kernel<<<(N_EDGES * 32 + 255) / 256, 256>>>(senders, receivers, out);
    finalize_kernel<<<(N_NODES + RPB - 1) / RPB, 128>>>(nodes, out);
    gnew_kernel<<<1, 128>>>(globals_, Wgw, Wgb, out + (size_t)N_NODES * D);
}

// round 8
// speedup vs baseline: 1.2117x; 1.2117x over previous
#include <cuda_runtime.h>
#include <cuda_bf16.h>
#include <cstdint>

#define N_NODES 100000
#define N_EDGES 640000
#define D 128
#define TILE_M 128
#define NTILES ((N_NODES + TILE_M - 1) / TILE_M)

// ---------------- scratch (device globals; no dynamic allocation) ----------
__device__ float g_conv[N_NODES * D];   // (nodes@W2 + b2) * rsqrt(send_deg)
__device__ float g_degs[N_NODES];       // rsqrt(max(send_deg,1))
__device__ float g_degr[N_NODES];       // rsqrt(max(recv_deg,1))
__device__ float g_gvec[D];             // globals@W3 + b3 + b1  (folded)
__device__ float g_an[D];               // column sum of h
// smem-image copies of weights, transposed to [n][k], bf16 hi/lo, XOR-swizzled:
// W1h, W1l, W2h, W2l -- each 128 rows x 256 bytes = 32 KB
__device__ __align__(16) unsigned char g_Wimg[4 * 32768];

// swizzled byte offset of element (row, k) in a 128x128 bf16 image (256B rows)
__device__ __forceinline__ uint32_t swz_off(int row, int k) {
    return (uint32_t)row * 256u + (((uint32_t)k * 2u) ^ (((uint32_t)row & 7u) * 16u));
}
__device__ __forceinline__ uint32_t smem_u32(const void* p) {
    uint32_t a;
    asm("{ .reg .u64 t; cvta.to.shared.u64 t, %1; cvt.u32.u64 %0, t; }" : "=r"(a) : "l"(p));
    return a;
}
__device__ __forceinline__ void ldsm4(uint32_t& r0, uint32_t& r1, uint32_t& r2,
                                      uint32_t& r3, uint32_t addr) {
    asm volatile("ldmatrix.sync.aligned.m8n8.x4.shared.b16 {%0,%1,%2,%3}, [%4];"
                 : "=r"(r0), "=r"(r1), "=r"(r2), "=r"(r3) : "r"(addr));
}
__device__ __forceinline__ void mma16816(float* c, const uint32_t* a,
                                         const uint32_t* b) {
    asm volatile(
        "mma.sync.aligned.m16n8k16.row.col.f32.bf16.bf16.f32 "
        "{%0,%1,%2,%3}, {%4,%5,%6,%7}, {%8,%9}, {%0,%1,%2,%3};"
        : "+f"(c[0]), "+f"(c[1]), "+f"(c[2]), "+f"(c[3])
        : "r"(a[0]), "r"(a[1]), "r"(a[2]), "r"(a[3]), "r"(b[0]), "r"(b[1]));
}

// ---------------- init ------------------------------------------------------
__global__ void zero_kernel() {
    int i = blockIdx.x * blockDim.x + threadIdx.x;
    if (i < N_NODES) { g_degs[i] = 0.f; g_degr[i] = 0.f; }
    if (i < D) g_an[i] = 0.f;
}
__global__ void degree_kernel(const int* __restrict__ senders,
                              const int* __restrict__ receivers) {
    int e = blockIdx.x * blockDim.x + threadIdx.x;
    if (e < N_EDGES) {
        atomicAdd(&g_degs[senders[e]], 1.f);
        atomicAdd(&g_degr[receivers[e]], 1.f);
    }
}
__global__ void rs_kernel() {
    int i = blockIdx.x * blockDim.x + threadIdx.x;
    if (i < N_NODES) {
        g_degs[i] = rsqrtf(fmaxf(g_degs[i], 1.f));
        g_degr[i] = rsqrtf(fmaxf(g_degr[i], 1.f));
    }
}

// ---------------- weight prep: fp32 W[k][n] -> bf16 hi/lo images Bt[n][k] ---
__global__ void wprep_kernel(const float* __restrict__ W1,
                             const float* __restrict__ W2) {
    int mat = blockIdx.x;                     // 0: W1, 1: W2
    const float* W = mat ? W2 : W1;
    unsigned char* hi = g_Wimg + (size_t)(mat * 2) * 32768;
    unsigned char* lo = hi + 32768;
    for (int idx = threadIdx.x; idx < D * D; idx += blockDim.x) {
        int k = idx >> 7, n = idx & 127;      // coalesced read of W[k][n]
        float w = W[k * D + n];
        __nv_bfloat16 h = __float2bfloat16_rn(w);
        __nv_bfloat16 l = __float2bfloat16_rn(w - __bfloat162float(h));
        uint32_t off = swz_off(n, k);
        *(__nv_bfloat16*)(hi + off) = h;
        *(__nv_bfloat16*)(lo + off) = l;
    }
}

// ---------------- gvec: g_gvec = globals@W3 + b3 + b1 (warp per column) -----
__global__ void gvec_kernel(const float* __restrict__ g,
                            const float* __restrict__ W3,
                            const float* __restrict__ b3,
                            const float* __restrict__ b1) {
    int wid = threadIdx.x >> 5, lane = threadIdx.x & 31;
    int c = blockIdx.x * 4 + wid;
    float s = 0.f;
#pragma unroll
    for (int k = lane; k < D; k += 32) s += g[k] * W3[k * D + c];
#pragma unroll
    for (int o = 16; o; o >>= 1) s += __shfl_xor_sync(0xffffffffu, s, o);
    if (lane == 0) g_gvec[c] = s + b3[c] + b1[c];
}

// ---------------- HMMA dual GEMM -------------------------------------------
// CTA: 128 rows. 8 warps x 32 cols of the 256-wide combined output
// (warps 0-3: nodes@W1 -> out, warps 4-7: nodes@W2 -> g_conv).
// split-bf16 3-term: AhWh + AhWl + AlWh.
#define SM_AHI  0
#define SM_ALO  32768
#define SM_W    65536                       // W1h,W1l,W2h,W2l (131072 B)
#define SM_BIAS (SM_W + 4 * 32768)          // 256 floats: gvec | b2
#define SM_DEG  (SM_BIAS + 1024)            // 128 floats
#define SM_TOTAL (SM_DEG + 512)

__global__ __launch_bounds__(256, 1)
void gemm_hmma_kernel(const float* __restrict__ nodes,
                      const float* __restrict__ b2,
                      float* __restrict__ out) {
    extern __shared__ unsigned char smem[];
    uint32_t sbase = smem_u32(smem);
    int tid = threadIdx.x, wid = tid >> 5, lane = tid & 31;
    int row0 = blockIdx.x * TILE_M;
    float* sbias = (float*)(smem + SM_BIAS);
    float* sdeg  = (float*)(smem + SM_DEG);

    // ---- prologue: stage biases, degs, weight images, A hi/lo -------------
    if (tid < D) {
        sbias[tid] = g_gvec[tid];
        sbias[D + tid] = b2[tid];
        int gr = row0 + tid;
        sdeg[tid] = (gr < N_NODES) ? g_degs[gr] : 0.f;
    }
    {
        const float4* src = (const float4*)g_Wimg;
        float4* dst = (float4*)(smem + SM_W);
#pragma unroll
        for (int i = tid; i < (4 * 32768) / 16; i += 256) dst[i] = src[i];
    }
    {
        const float4* n4 = (const float4*)nodes;
        for (int i = tid; i < TILE_M * (D / 4); i += 256) {
            int r = i >> 5, q = i & 31;          // q: group of 4 k-values
            int gr = row0 + r;
            float4 v = (gr < N_NODES) ? n4[(size_t)gr * (D / 4) + q]
                                      : make_float4(0.f, 0.f, 0.f, 0.f);
            __nv_bfloat16 h0 = __float2bfloat16_rn(v.x), h1 = __float2bfloat16_rn(v.y);
            __nv_bfloat16 h2 = __float2bfloat16_rn(v.z), h3 = __float2bfloat16_rn(v.w);
            __nv_bfloat16 l0 = __float2bfloat16_rn(v.x - __bfloat162float(h0));
            __nv_bfloat16 l1 = __float2bfloat16_rn(v.y - __bfloat162float(h1));
            __nv_bfloat16 l2 = __float2bfloat16_rn(v.z - __bfloat162float(h2));
            __nv_bfloat16 l3 = __float2bfloat16_rn(v.w - __bfloat162float(h3));
            uint32_t off = (uint32_t)r * 256u + (((uint32_t)q * 8u) ^ (((uint32_t)r & 7u) * 16u));
            __nv_bfloat162 ph0{h0, h1}, ph1{h2, h3}, pl0{l0, l1}, pl1{l2, l3};
            uint2 uh{*(uint32_t*)&ph0, *(uint32_t*)&ph1};
            uint2 ul{*(uint32_t*)&pl0, *(uint32_t*)&pl1};
            *(uint2*)(smem + SM_AHI + off) = uh;
            *(uint2*)(smem + SM_ALO + off) = ul;
        }
    }
    __syncthreads();

    // ---- mainloop ----------------------------------------------------------
    int g = lane >> 3, i8 = lane & 7;
    int rA = i8 + 8 * (g & 1);                 // A ldmatrix row-in-tile
    int rB = i8 + 8 * (g >> 1);                // B ldmatrix row-in-tile
    int wn = (wid & 3) * 32;                   // warp's 32-col block
    bool isW2 = wid >= 4;
    uint32_t aHI = sbase + SM_AHI, aLO = sbase + SM_ALO;
    uint32_t wH = sbase + SM_W + (isW2 ? 2 : 0) * 32768;
    uint32_t wL = wH + 32768;
    uint32_t swzA = (uint32_t)i8 * 16u;

    float c[8][4][4];
#pragma unroll
    for (int mi = 0; mi < 8; mi++)
#pragma unroll
        for (int ni = 0; ni < 4; ni++)
#pragma unroll
            for (int q = 0; q < 4; q++) c[mi][ni][q] = 0.f;

#pragma unroll
    for (int ks = 0; ks < 8; ks++) {
        uint32_t kA = ((uint32_t)(ks * 32 + (g >> 1) * 16)) ^ swzA;
        uint32_t kB = ((uint32_t)(ks * 32 + (g & 1) * 16)) ^ swzA;
        // B frags: Wh and Wl, 2 n-tiles of 16 cols each
        uint32_t bh[4][2], bl[4][2];
#pragma unroll
        for (int nt = 0; nt < 2; nt++) {
            uint32_t rowoff = (uint32_t)(wn + nt * 16 + rB) * 256u;
            ldsm4(bh[nt * 2][0], bh[nt * 2][1], bh[nt * 2 + 1][0], bh[nt * 2 + 1][1],
                  wH + rowoff + kB);
            ldsm4(bl[nt * 2][0], bl[nt * 2][1], bl[nt * 2 + 1][0], bl[nt * 2 + 1][1],
                  wL + rowoff + kB);
        }
        uint32_t a[8][4];
        // A-hi frags, then AhWh + AhWl
#pragma unroll
        for (int mi = 0; mi < 8; mi++)
            ldsm4(a[mi][0], a[mi][1], a[mi][2], a[mi][3],
                  aHI + (uint32_t)(mi * 16 + rA) * 256u + kA);
#pragma unroll
        for (int mi = 0; mi < 8; mi++)
#pragma unroll
            for (int ni = 0; ni < 4; ni++) {
                mma16816(c[mi][ni], a[mi], bh[ni]);
                mma16816(c[mi][ni], a[mi], bl[ni]);
            }
        // A-lo frags, AlWh
#pragma unroll
        for (int mi = 0; mi < 8; mi++)
            ldsm4(a[mi][0], a[mi][1], a[mi][2], a[mi][3],
                  aLO + (uint32_t)(mi * 16 + rA) * 256u + kA);
#pragma unroll
        for (int mi = 0; mi < 8; mi++)
#pragma unroll
            for (int ni = 0; ni < 4; ni++)
                mma16816(c[mi][ni], a[mi], bh[ni]);
    }

    // ---- epilogue ----------------------------------------------------------
    int groupr = lane >> 2, qc = lane & 3;
#pragma unroll
    for (int mi = 0; mi < 8; mi++) {
        int r1 = mi * 16 + groupr, r2 = r1 + 8;
        int gr1 = row0 + r1, gr2 = row0 + r2;
        float rv1 = sdeg[r1], rv2 = sdeg[r2];
#pragma unroll
        for (int ni = 0; ni < 4; ni++) {
            int cc = wn + ni * 8 + qc * 2;     // 0..127 within this matrix
            float* acc = c[mi][ni];
            if (!isW2) {
                float2 v1{acc[0] + sbias[cc], acc[1] + sbias[cc + 1]};
                float2 v2{acc[2] + sbias[cc], acc[3] + sbias[cc + 1]};
                if (gr1 < N_NODES) *(float2*)&out[(size_t)gr1 * D + cc] = v1;
                if (gr2 < N_NODES) *(float2*)&out[(size_t)gr2 * D + cc] = v2;
            } else {
                float2 v1{(acc[0] + sbias[D + cc]) * rv1,
                          (acc[1] + sbias[D + cc + 1]) * rv1};
                float2 v2{(acc[2] + sbias[D + cc]) * rv2,
                          (acc[3] + sbias[D + cc + 1]) * rv2};
                if (gr1 < N_NODES) *(float2*)&g_conv[(size_t)gr1 * D + cc] = v1;
                if (gr2 < N_NODES) *(float2*)&g_conv[(size_t)gr2 * D + cc] = v2;
            }
        }
    }
}

// ---------------- edge scatter: out[r] += conv[s] * rsqrt(recv_deg[r]) -----
__global__ void edge_kernel(const int* __restrict__ senders,
                            const int* __restrict__ receivers,
                            float* __restrict__ out) {
    int t = blockIdx.x * blockDim.x + threadIdx.x;
    int e = t >> 5, lane = t & 31;
    if (e >= N_EDGES) return;
    int s = __ldg(&senders[e]);
    int r = __ldg(&receivers[e]);
    float rr = g_degr[r];
    float4 v = *(const float4*)&g_conv[(size_t)s * D + lane * 4];
    float* dst = &out[(size_t)r * D + lane * 4];
    asm volatile("red.global.add.v4.f32 [%0], {%1,%2,%3,%4};"
                 :: "l"(dst), "f"(v.x * rr), "f"(v.y * rr), "f"(v.z * rr), "f"(v.w * rr)
                 : "memory");
}

// ---------------- finalize: h = relu(h1+agg) + nodes ; an = colsum(h) ------
#define RPB 64
__global__ void finalize_kernel(const float* __restrict__ nodes,
                                float* __restrict__ out) {
    int c = threadIdx.x;
    int row0 = blockIdx.x * RPB;
    float s = 0.f;
#pragma unroll 4
    for (int r = 0; r < RPB; r++) {
        int gr = row0 + r;
        if (gr >= N_NODES) break;
        size_t idx = (size_t)gr * D + c;
        float v = fmaxf(out[idx], 0.f) + nodes[idx];
        out[idx] = v;
        s += v;
    }
    atomicAdd(&g_an[c], s);
}

// ---------------- global update: g_new = g + relu([an; g] @ Wg + bg) -------
__global__ void gnew_kernel(const float* __restrict__ g,
                            const float* __restrict__ Wg,
                            const float* __restrict__ bg,
                            float* __restrict__ out2) {
    __shared__ float sv[2 * D];
    int c = threadIdx.x;
    sv[c] = g_an[c];
    sv[D + c] = g[c];
    __syncthreads();
    float acc = bg[c];
#pragma unroll 8
    for (int k = 0; k < 2 * D; k++) acc += sv[k] * Wg[k * D + c];
    out2[c] = g[c] + fmaxf(acc, 0.f);
}

// ---------------- launch ----------------------------------------------------
extern "C" void kernel_launch(void* const* d_in, const int* in_sizes, int n_in,
                              void* d_out, int out_size) {
    const float* nodes    = (const float*)d_in[0];
    const float* globals_ = (const float*)d_in[1];
    const int*   senders   = (const int*)d_in[2];
    const int*   receivers = (const int*)d_in[3];
    const float* W1w = (const float*)d_in[4];
    const float* W1b = (const float*)d_in[5];
    const float* W2w = (const float*)d_in[6];
    const float* W2b = (const float*)d_in[7];
    const float* W3w = (const float*)d_in[8];
    const float* W3b = (const float*)d_in[9];
    const float* Wgw = (const float*)d_in[10];
    const float* Wgb = (const float*)d_in[11];
    float* out = (float*)d_out;

    cudaFuncSetAttribute(gemm_hmma_kernel, cudaFuncAttributeMaxDynamicSharedMemorySize,
                         SM_TOTAL);

    zero_kernel<<<(N_NODES + 255) / 256, 256>>>();
    degree_kernel<<<(N_EDGES + 255) / 256, 256>>>(senders, receivers);
    rs_kernel<<<(N_NODES + 255) / 256, 256>>>();
    wprep_kernel<<<2, 256>>>(W1w, W2w);
    gvec_kernel<<<D / 4, 128>>>(globals_, W3w, W3b, W1b);
    gemm_hmma_kernel<<<NTILES, 256, SM_TOTAL>>>(nodes, W2b, out);
    edge_kernel<<<(N_EDGES * 32 + 255) / 256, 256>>>(senders, receivers, out);
    finalize_kernel<<<(N_NODES + RPB - 1) / RPB, 128>>>(nodes, out);
    gnew_kernel<<<1, 128>>>(globals_, Wgw, Wgb, out + (size_t)N_NODES * D);
}

// round 9
// speedup vs baseline: 1.5711x; 1.2966x over previous
#include <cuda_runtime.h>
#include <cuda_bf16.h>
#include <cstdint>

#define N_NODES 100000
#define N_EDGES 640000
#define D 128
#define TILE_M 128
#define NTILES ((N_NODES + TILE_M - 1) / TILE_M)

// ---------------- scratch (device globals; no dynamic allocation) ----------
__device__ float g_conv[N_NODES * D];   // (nodes@W2 + b2) * rsqrt(send_deg)
__device__ float g_degs[N_NODES];       // rsqrt(max(send_deg,1))
__device__ float g_degr[N_NODES];       // rsqrt(max(recv_deg,1))
__device__ float g_gvec[D];             // globals@W3 + b3 + b1  (folded)
__device__ float g_an[D];               // column sum of h
// smem-image copies of weights, transposed to [n][k], bf16 hi/lo, XOR-swizzled:
// W1h, W1l, W2h, W2l -- each 128 rows x 256 bytes = 32 KB
__device__ __align__(16) unsigned char g_Wimg[4 * 32768];

// swizzled byte offset of element (row, k) in a 128x128 bf16 image (256B rows)
__device__ __forceinline__ uint32_t swz_off(int row, int k) {
    return (uint32_t)row * 256u + (((uint32_t)k * 2u) ^ (((uint32_t)row & 7u) * 16u));
}
__device__ __forceinline__ uint32_t smem_u32(const void* p) {
    uint32_t a;
    asm("{ .reg .u64 t; cvta.to.shared.u64 t, %1; cvt.u32.u64 %0, t; }" : "=r"(a) : "l"(p));
    return a;
}
__device__ __forceinline__ void ldsm4(uint32_t& r0, uint32_t& r1, uint32_t& r2,
                                      uint32_t& r3, uint32_t addr) {
    asm volatile("ldmatrix.sync.aligned.m8n8.x4.shared.b16 {%0,%1,%2,%3}, [%4];"
                 : "=r"(r0), "=r"(r1), "=r"(r2), "=r"(r3) : "r"(addr));
}
__device__ __forceinline__ void mma16816(float* c, const uint32_t* a,
                                         const uint32_t* b) {
    asm volatile(
        "mma.sync.aligned.m16n8k16.row.col.f32.bf16.bf16.f32 "
        "{%0,%1,%2,%3}, {%4,%5,%6,%7}, {%8,%9}, {%0,%1,%2,%3};"
        : "+f"(c[0]), "+f"(c[1]), "+f"(c[2]), "+f"(c[3])
        : "r"(a[0]), "r"(a[1]), "r"(a[2]), "r"(a[3]), "r"(b[0]), "r"(b[1]));
}

// ---------------- init ------------------------------------------------------
__global__ void zero_kernel() {
    int i = blockIdx.x * blockDim.x + threadIdx.x;
    if (i < N_NODES) { g_degs[i] = 0.f; g_degr[i] = 0.f; }
    if (i < D) g_an[i] = 0.f;
}
__global__ void degree_kernel(const int* __restrict__ senders,
                              const int* __restrict__ receivers) {
    int e = blockIdx.x * blockDim.x + threadIdx.x;
    if (e < N_EDGES) {
        atomicAdd(&g_degs[senders[e]], 1.f);
        atomicAdd(&g_degr[receivers[e]], 1.f);
    }
}
__global__ void rs_kernel() {
    int i = blockIdx.x * blockDim.x + threadIdx.x;
    if (i < N_NODES) {
        g_degs[i] = rsqrtf(fmaxf(g_degs[i], 1.f));
        g_degr[i] = rsqrtf(fmaxf(g_degr[i], 1.f));
    }
}

// ---------------- weight prep: fp32 W[k][n] -> bf16 hi/lo images Bt[n][k] ---
// grid = 128 blocks x 256 threads: one element per thread
__global__ void wprep_kernel(const float* __restrict__ W1,
                             const float* __restrict__ W2) {
    int mat = blockIdx.x & 1;                 // 0: W1, 1: W2
    int idx = (blockIdx.x >> 1) * 256 + threadIdx.x;   // 0..16383
    const float* W = mat ? W2 : W1;
    unsigned char* hi = g_Wimg + (size_t)(mat * 2) * 32768;
    unsigned char* lo = hi + 32768;
    int k = idx >> 7, n = idx & 127;          // coalesced read of W[k][n]
    float w = W[k * D + n];
    __nv_bfloat16 h = __float2bfloat16_rn(w);
    __nv_bfloat16 l = __float2bfloat16_rn(w - __bfloat162float(h));
    uint32_t off = swz_off(n, k);
    *(__nv_bfloat16*)(hi + off) = h;
    *(__nv_bfloat16*)(lo + off) = l;
}

// ---------------- gvec: g_gvec = globals@W3 + b3 + b1 (warp per column) -----
__global__ void gvec_kernel(const float* __restrict__ g,
                            const float* __restrict__ W3,
                            const float* __restrict__ b3,
                            const float* __restrict__ b1) {
    int wid = threadIdx.x >> 5, lane = threadIdx.x & 31;
    int c = blockIdx.x * 4 + wid;
    float s = 0.f;
#pragma unroll
    for (int k = lane; k < D; k += 32) s += g[k] * W3[k * D + c];
#pragma unroll
    for (int o = 16; o; o >>= 1) s += __shfl_xor_sync(0xffffffffu, s, o);
    if (lane == 0) g_gvec[c] = s + b3[c] + b1[c];
}

// ---------------- HMMA dual GEMM (512 threads, 16 warps) --------------------
// CTA: 128 rows x 256 combined cols. Warp tile: 32 rows x 64 cols.
//   wm = wid & 3  -> row block 32*wm
//   wc = wid >> 2 -> col block 64*wc of 256 (wc 0,1: W1 -> out; 2,3: W2 -> g_conv)
// split-bf16 3-term: AhWh + AhWl + AlWh.
#define SM_AHI  0
#define SM_ALO  32768
#define SM_W    65536                       // W1h,W1l,W2h,W2l (131072 B)
#define SM_BIAS (SM_W + 4 * 32768)          // 256 floats: gvec | b2
#define SM_DEG  (SM_BIAS + 1024)            // 128 floats
#define SM_TOTAL (SM_DEG + 512)
#define GT 512

__global__ __launch_bounds__(GT, 1)
void gemm_hmma_kernel(const float* __restrict__ nodes,
                      const float* __restrict__ b2,
                      float* __restrict__ out) {
    extern __shared__ unsigned char smem[];
    uint32_t sbase = smem_u32(smem);
    int tid = threadIdx.x, wid = tid >> 5, lane = tid & 31;
    int row0 = blockIdx.x * TILE_M;
    float* sbias = (float*)(smem + SM_BIAS);
    float* sdeg  = (float*)(smem + SM_DEG);

    // ---- prologue: stage biases, degs, weight images, A hi/lo -------------
    if (tid < D) {
        sbias[tid] = g_gvec[tid];
        sbias[D + tid] = b2[tid];
        int gr = row0 + tid;
        sdeg[tid] = (gr < N_NODES) ? g_degs[gr] : 0.f;
    }
    {
        const float4* src = (const float4*)g_Wimg;
        float4* dst = (float4*)(smem + SM_W);
#pragma unroll
        for (int i = tid; i < (4 * 32768) / 16; i += GT) dst[i] = src[i];
    }
    {
        const float4* n4 = (const float4*)nodes;
#pragma unroll
        for (int i = tid; i < TILE_M * (D / 4); i += GT) {
            int r = i >> 5, q = i & 31;          // q: group of 4 k-values
            int gr = row0 + r;
            float4 v = (gr < N_NODES) ? n4[(size_t)gr * (D / 4) + q]
                                      : make_float4(0.f, 0.f, 0.f, 0.f);
            __nv_bfloat16 h0 = __float2bfloat16_rn(v.x), h1 = __float2bfloat16_rn(v.y);
            __nv_bfloat16 h2 = __float2bfloat16_rn(v.z), h3 = __float2bfloat16_rn(v.w);
            __nv_bfloat16 l0 = __float2bfloat16_rn(v.x - __bfloat162float(h0));
            __nv_bfloat16 l1 = __float2bfloat16_rn(v.y - __bfloat162float(h1));
            __nv_bfloat16 l2 = __float2bfloat16_rn(v.z - __bfloat162float(h2));
            __nv_bfloat16 l3 = __float2bfloat16_rn(v.w - __bfloat162float(h3));
            uint32_t off = (uint32_t)r * 256u + (((uint32_t)q * 8u) ^ (((uint32_t)r & 7u) * 16u));
            __nv_bfloat162 ph0{h0, h1}, ph1{h2, h3}, pl0{l0, l1}, pl1{l2, l3};
            uint2 uh{*(uint32_t*)&ph0, *(uint32_t*)&ph1};
            uint2 ul{*(uint32_t*)&pl0, *(uint32_t*)&pl1};
            *(uint2*)(smem + SM_AHI + off) = uh;
            *(uint2*)(smem + SM_ALO + off) = ul;
        }
    }
    __syncthreads();

    // ---- mainloop ----------------------------------------------------------
    int g = lane >> 3, i8 = lane & 7;
    int rA = i8 + 8 * (g & 1);                 // A ldmatrix row-in-tile
    int rB = i8 + 8 * (g >> 1);                // B ldmatrix row-in-tile
    int wm = (wid & 3) * 32;                   // warp's 32-row block
    int wc = wid >> 2;                         // 64-col block of 256
    bool isW2 = wc >= 2;
    int wn = (wc & 1) * 64;                    // col offset within matrix
    uint32_t aHI = sbase + SM_AHI, aLO = sbase + SM_ALO;
    uint32_t wH = sbase + SM_W + (isW2 ? 2 : 0) * 32768;
    uint32_t wL = wH + 32768;
    uint32_t swzA = (uint32_t)i8 * 16u;

    float c[2][8][4];
#pragma unroll
    for (int mi = 0; mi < 2; mi++)
#pragma unroll
        for (int ni = 0; ni < 8; ni++)
#pragma unroll
            for (int q = 0; q < 4; q++) c[mi][ni][q] = 0.f;

#pragma unroll
    for (int ks = 0; ks < 8; ks++) {
        uint32_t kA = ((uint32_t)(ks * 32 + (g >> 1) * 16)) ^ swzA;
        uint32_t kB = ((uint32_t)(ks * 32 + (g & 1) * 16)) ^ swzA;
        // B frags: Wh and Wl, 4 n-tiles of 16 cols each -> 8 n8-tiles
        uint32_t bh[8][2], bl[8][2];
#pragma unroll
        for (int nt = 0; nt < 4; nt++) {
            uint32_t rowoff = (uint32_t)(wn + nt * 16 + rB) * 256u;
            ldsm4(bh[nt * 2][0], bh[nt * 2][1], bh[nt * 2 + 1][0], bh[nt * 2 + 1][1],
                  wH + rowoff + kB);
            ldsm4(bl[nt * 2][0], bl[nt * 2][1], bl[nt * 2 + 1][0], bl[nt * 2 + 1][1],
                  wL + rowoff + kB);
        }
        uint32_t a[2][4];
        // A-hi frags, then AhWh + AhWl
#pragma unroll
        for (int mi = 0; mi < 2; mi++)
            ldsm4(a[mi][0], a[mi][1], a[mi][2], a[mi][3],
                  aHI + (uint32_t)(wm + mi * 16 + rA) * 256u + kA);
#pragma unroll
        for (int mi = 0; mi < 2; mi++)
#pragma unroll
            for (int ni = 0; ni < 8; ni++) {
                mma16816(c[mi][ni], a[mi], bh[ni]);
                mma16816(c[mi][ni], a[mi], bl[ni]);
            }
        // A-lo frags, AlWh
#pragma unroll
        for (int mi = 0; mi < 2; mi++)
            ldsm4(a[mi][0], a[mi][1], a[mi][2], a[mi][3],
                  aLO + (uint32_t)(wm + mi * 16 + rA) * 256u + kA);
#pragma unroll
        for (int mi = 0; mi < 2; mi++)
#pragma unroll
            for (int ni = 0; ni < 8; ni++)
                mma16816(c[mi][ni], a[mi], bh[ni]);
    }

    // ---- epilogue ----------------------------------------------------------
    int groupr = lane >> 2, qc = lane & 3;
#pragma unroll
    for (int mi = 0; mi < 2; mi++) {
        int r1 = wm + mi * 16 + groupr, r2 = r1 + 8;
        int gr1 = row0 + r1, gr2 = row0 + r2;
        float rv1 = sdeg[r1], rv2 = sdeg[r2];
#pragma unroll
        for (int ni = 0; ni < 8; ni++) {
            int cc = wn + ni * 8 + qc * 2;     // 0..127 within this matrix
            float* acc = c[mi][ni];
            if (!isW2) {
                float2 v1{acc[0] + sbias[cc], acc[1] + sbias[cc + 1]};
                float2 v2{acc[2] + sbias[cc], acc[3] + sbias[cc + 1]};
                if (gr1 < N_NODES) *(float2*)&out[(size_t)gr1 * D + cc] = v1;
                if (gr2 < N_NODES) *(float2*)&out[(size_t)gr2 * D + cc] = v2;
            } else {
                float2 v1{(acc[0] + sbias[D + cc]) * rv1,
                          (acc[1] + sbias[D + cc + 1]) * rv1};
                float2 v2{(acc[2] + sbias[D + cc]) * rv2,
                          (acc[3] + sbias[D + cc + 1]) * rv2};
                if (gr1 < N_NODES) *(float2*)&g_conv[(size_t)gr1 * D + cc] = v1;
                if (gr2 < N_NODES) *(float2*)&g_conv[(size_t)gr2 * D + cc] = v2;
            }
        }
    }
}

// ---------------- edge scatter: out[r] += conv[s] * rsqrt(recv_deg[r]) -----
__global__ void edge_kernel(const int* __restrict__ senders,
                            const int* __restrict__ receivers,
                            float* __restrict__ out) {
    int t = blockIdx.x * blockDim.x + threadIdx.x;
    int e = t >> 5, lane = t & 31;
    if (e >= N_EDGES) return;
    int s = __ldg(&senders[e]);
    int r = __ldg(&receivers[e]);
    float rr = g_degr[r];
    float4 v = *(const float4*)&g_conv[(size_t)s * D + lane * 4];
    float* dst = &out[(size_t)r * D + lane * 4];
    asm volatile("red.global.add.v4.f32 [%0], {%1,%2,%3,%4};"
                 :: "l"(dst), "f"(v.x * rr), "f"(v.y * rr), "f"(v.z * rr), "f"(v.w * rr)
                 : "memory");
}

// ---------------- finalize: h = relu(h1+agg) + nodes ; an = colsum(h) ------
#define RPB 64
__global__ void finalize_kernel(const float* __restrict__ nodes,
                                float* __restrict__ out) {
    int c = threadIdx.x;
    int row0 = blockIdx.x * RPB;
    float s = 0.f;
#pragma unroll 4
    for (int r = 0; r < RPB; r++) {
        int gr = row0 + r;
        if (gr >= N_NODES) break;
        size_t idx = (size_t)gr * D + c;
        float v = fmaxf(out[idx], 0.f) + nodes[idx];
        out[idx] = v;
        s += v;
    }
    atomicAdd(&g_an[c], s);
}

// ---------------- global update: g_new = g + relu([an; g] @ Wg + bg) -------
__global__ void gnew_kernel(const float* __restrict__ g,
                            const float* __restrict__ Wg,
                            const float* __restrict__ bg,
                            float* __restrict__ out2) {
    __shared__ float sv[2 * D];
    int c = threadIdx.x;
    sv[c] = g_an[c];
    sv[D + c] = g[c];
    __syncthreads();
    float acc = bg[c];
#pragma unroll 8
    for (int k = 0; k < 2 * D; k++) acc += sv[k] * Wg[k * D + c];
    out2[c] = g[c] + fmaxf(acc, 0.f);
}

// ---------------- launch ----------------------------------------------------
extern "C" void kernel_launch(void* const* d_in, const int* in_sizes, int n_in,
                              void* d_out, int out_size) {
    const float* nodes    = (const float*)d_in[0];
    const float* globals_ = (const float*)d_in[1];
    const int*   senders   = (const int*)d_in[2];
    const int*   receivers = (const int*)d_in[3];
    const float* W1w = (const float*)d_in[4];
    const float* W1b = (const float*)d_in[5];
    const float* W2w = (const float*)d_in[6];
    const float* W2b = (const float*)d_in[7];
    const float* W3w = (const float*)d_in[8];
    const float* W3b = (const float*)d_in[9];
    const float* Wgw = (const float*)d_in[10];
    const float* Wgb = (const float*)d_in[11];
    float* out = (float*)d_out;

    cudaFuncSetAttribute(gemm_hmma_kernel, cudaFuncAttributeMaxDynamicSharedMemorySize,
                         SM_TOTAL);

    zero_kernel<<<(N_NODES + 255) / 256, 256>>>();
    degree_kernel<<<(N_EDGES + 255) / 256, 256>>>(senders, receivers);
    rs_kernel<<<(N_NODES + 255) / 256, 256>>>();
    wprep_kernel<<<128, 256>>>(W1w, W2w);
    gvec_kernel<<<D / 4, 128>>>(globals_, W3w, W3b, W1b);
    gemm_hmma_kernel<<<NTILES, GT, SM_TOTAL>>>(nodes, W2b, out);
    edge_kernel<<<(N_EDGES * 32 + 255) / 256, 256>>>(senders, receivers, out);
    finalize_kernel<<<(N_NODES + RPB - 1) / RPB, 128>>>(nodes, out);
    gnew_kernel<<<1, 128>>>(globals_, Wgw, Wgb, out + (size_t)N_NODES * D);
}

// round 10
// speedup vs baseline: 1.9483x; 1.2401x over previous
#include <cuda_runtime.h>
#include <cuda_bf16.h>
#include <cstdint>

#define N_NODES 100000
#define N_EDGES 640000
#define D 128
#define TILE_M 128
#define NTILES ((N_NODES + TILE_M - 1) / TILE_M)
#define SCAN_B 98                      // ceil(100000/1024)

// ---------------- scratch (device globals; no dynamic allocation) ----------
__device__ float g_conv[N_NODES * D];   // (nodes@W2 + b2) * rsqrt(send_deg)
__device__ float g_degs[N_NODES];       // rsqrt(max(send_deg,1))
__device__ float g_degr[N_NODES];       // rsqrt(max(recv_deg,1))
__device__ float g_gvec[D];             // globals@W3 + b3 + b1  (folded)
__device__ float g_an[D];               // column sum of h
__device__ int   g_cnt_s[N_NODES];      // send degree (int)
__device__ int   g_cnt_r[N_NODES];      // recv degree (int)
__device__ int   g_rowstart[N_NODES + 1];
__device__ int   g_cursor[N_NODES];
__device__ int   g_bsum[128], g_bscan[128];
__device__ int   g_csr[N_EDGES];        // sender ids bucketed by receiver
// weight images, transposed to [n][k], bf16 hi/lo, XOR-swizzled: W1h,W1l,W2h,W2l
__device__ __align__(16) unsigned char g_Wimg[4 * 32768];

// swizzled byte offset of element (row, k) in a 128x128 bf16 image (256B rows)
__device__ __forceinline__ uint32_t swz_off(int row, int k) {
    return (uint32_t)row * 256u + (((uint32_t)k * 2u) ^ (((uint32_t)row & 7u) * 16u));
}
__device__ __forceinline__ uint32_t smem_u32(const void* p) {
    uint32_t a;
    asm("{ .reg .u64 t; cvta.to.shared.u64 t, %1; cvt.u32.u64 %0, t; }" : "=r"(a) : "l"(p));
    return a;
}
__device__ __forceinline__ void ldsm4(uint32_t& r0, uint32_t& r1, uint32_t& r2,
                                      uint32_t& r3, uint32_t addr) {
    asm volatile("ldmatrix.sync.aligned.m8n8.x4.shared.b16 {%0,%1,%2,%3}, [%4];"
                 : "=r"(r0), "=r"(r1), "=r"(r2), "=r"(r3) : "r"(addr));
}
__device__ __forceinline__ void mma16816(float* c, const uint32_t* a,
                                         const uint32_t* b) {
    asm volatile(
        "mma.sync.aligned.m16n8k16.row.col.f32.bf16.bf16.f32 "
        "{%0,%1,%2,%3}, {%4,%5,%6,%7}, {%8,%9}, {%0,%1,%2,%3};"
        : "+f"(c[0]), "+f"(c[1]), "+f"(c[2]), "+f"(c[3])
        : "r"(a[0]), "r"(a[1]), "r"(a[2]), "r"(a[3]), "r"(b[0]), "r"(b[1]));
}

// ---------------- init / degrees -------------------------------------------
__global__ void zero_kernel() {
    int i = blockIdx.x * blockDim.x + threadIdx.x;
    if (i < N_NODES) { g_cnt_s[i] = 0; g_cnt_r[i] = 0; }
    if (i < D) g_an[i] = 0.f;
}
__global__ void degree_kernel(const int* __restrict__ senders,
                              const int* __restrict__ receivers) {
    int e = blockIdx.x * blockDim.x + threadIdx.x;
    if (e < N_EDGES) {
        atomicAdd(&g_cnt_s[senders[e]], 1);
        atomicAdd(&g_cnt_r[receivers[e]], 1);
    }
}
__global__ void rs_kernel() {
    int i = blockIdx.x * blockDim.x + threadIdx.x;
    if (i < N_NODES) {
        g_degs[i] = rsqrtf(fmaxf((float)g_cnt_s[i], 1.f));
        g_degr[i] = rsqrtf(fmaxf((float)g_cnt_r[i], 1.f));
    }
}

// ---------------- exclusive scan of recv counts -> g_rowstart ---------------
__global__ __launch_bounds__(1024) void scan1_kernel() {
    __shared__ int tmp[1024];
    int t = threadIdx.x, i = blockIdx.x * 1024 + t;
    int v = (i < N_NODES) ? g_cnt_r[i] : 0;
    tmp[t] = v;
    __syncthreads();
#pragma unroll
    for (int off = 1; off < 1024; off <<= 1) {
        int x = (t >= off) ? tmp[t - off] : 0;
        __syncthreads();
        tmp[t] += x;
        __syncthreads();
    }
    if (i < N_NODES) g_rowstart[i] = tmp[t] - v;   // exclusive within block
    if (t == 1023) g_bsum[blockIdx.x] = tmp[t];
}
__global__ void scan2_kernel() {          // 1 block, 128 threads
    __shared__ int tmp[128];
    int t = threadIdx.x;
    int v = (t < SCAN_B) ? g_bsum[t] : 0;
    tmp[t] = v;
    __syncthreads();
#pragma unroll
    for (int off = 1; off < 128; off <<= 1) {
        int x = (t >= off) ? tmp[t - off] : 0;
        __syncthreads();
        tmp[t] += x;
        __syncthreads();
    }
    g_bscan[t] = tmp[t] - v;              // exclusive
}
__global__ __launch_bounds__(1024) void scan3_kernel() {
    int t = threadIdx.x, i = blockIdx.x * 1024 + t;
    if (i < N_NODES) {
        int v = g_rowstart[i] + g_bscan[blockIdx.x];
        g_rowstart[i] = v;
        g_cursor[i] = v;
    }
    if (i == N_NODES) g_rowstart[N_NODES] = N_EDGES;
}
__global__ void bucket_kernel(const int* __restrict__ senders,
                              const int* __restrict__ receivers) {
    int e = blockIdx.x * blockDim.x + threadIdx.x;
    if (e < N_EDGES) {
        int pos = atomicAdd(&g_cursor[receivers[e]], 1);
        g_csr[pos] = senders[e];
    }
}

// ---------------- weight prep: fp32 W[k][n] -> bf16 hi/lo images Bt[n][k] ---
__global__ void wprep_kernel(const float* __restrict__ W1,
                             const float* __restrict__ W2) {
    int mat = blockIdx.x & 1;                 // 0: W1, 1: W2
    int idx = (blockIdx.x >> 1) * 256 + threadIdx.x;   // 0..16383
    const float* W = mat ? W2 : W1;
    unsigned char* hi = g_Wimg + (size_t)(mat * 2) * 32768;
    unsigned char* lo = hi + 32768;
    int k = idx >> 7, n = idx & 127;          // coalesced read of W[k][n]
    float w = W[k * D + n];
    __nv_bfloat16 h = __float2bfloat16_rn(w);
    __nv_bfloat16 l = __float2bfloat16_rn(w - __bfloat162float(h));
    uint32_t off = swz_off(n, k);
    *(__nv_bfloat16*)(hi + off) = h;
    *(__nv_bfloat16*)(lo + off) = l;
}

// ---------------- gvec: g_gvec = globals@W3 + b3 + b1 (warp per column) -----
__global__ void gvec_kernel(const float* __restrict__ g,
                            const float* __restrict__ W3,
                            const float* __restrict__ b3,
                            const float* __restrict__ b1) {
    int wid = threadIdx.x >> 5, lane = threadIdx.x & 31;
    int c = blockIdx.x * 4 + wid;
    float s = 0.f;
#pragma unroll
    for (int k = lane; k < D; k += 32) s += g[k] * W3[k * D + c];
#pragma unroll
    for (int o = 16; o; o >>= 1) s += __shfl_xor_sync(0xffffffffu, s, o);
    if (lane == 0) g_gvec[c] = s + b3[c] + b1[c];
}

// ---------------- HMMA dual GEMM (512 threads, 16 warps) --------------------
#define SM_AHI  0
#define SM_ALO  32768
#define SM_W    65536                       // W1h,W1l,W2h,W2l (131072 B)
#define SM_BIAS (SM_W + 4 * 32768)          // 256 floats: gvec | b2
#define SM_DEG  (SM_BIAS + 1024)            // 128 floats
#define SM_TOTAL (SM_DEG + 512)
#define GT 512

__global__ __launch_bounds__(GT, 1)
void gemm_hmma_kernel(const float* __restrict__ nodes,
                      const float* __restrict__ b2,
                      float* __restrict__ out) {
    extern __shared__ unsigned char smem[];
    uint32_t sbase = smem_u32(smem);
    int tid = threadIdx.x, wid = tid >> 5, lane = tid & 31;
    int row0 = blockIdx.x * TILE_M;
    float* sbias = (float*)(smem + SM_BIAS);
    float* sdeg  = (float*)(smem + SM_DEG);

    if (tid < D) {
        sbias[tid] = g_gvec[tid];
        sbias[D + tid] = b2[tid];
        int gr = row0 + tid;
        sdeg[tid] = (gr < N_NODES) ? g_degs[gr] : 0.f;
    }
    {
        const float4* src = (const float4*)g_Wimg;
        float4* dst = (float4*)(smem + SM_W);
#pragma unroll
        for (int i = tid; i < (4 * 32768) / 16; i += GT) dst[i] = src[i];
    }
    {
        const float4* n4 = (const float4*)nodes;
#pragma unroll
        for (int i = tid; i < TILE_M * (D / 4); i += GT) {
            int r = i >> 5, q = i & 31;
            int gr = row0 + r;
            float4 v = (gr < N_NODES) ? n4[(size_t)gr * (D / 4) + q]
                                      : make_float4(0.f, 0.f, 0.f, 0.f);
            __nv_bfloat16 h0 = __float2bfloat16_rn(v.x), h1 = __float2bfloat16_rn(v.y);
            __nv_bfloat16 h2 = __float2bfloat16_rn(v.z), h3 = __float2bfloat16_rn(v.w);
            __nv_bfloat16 l0 = __float2bfloat16_rn(v.x - __bfloat162float(h0));
            __nv_bfloat16 l1 = __float2bfloat16_rn(v.y - __bfloat162float(h1));
            __nv_bfloat16 l2 = __float2bfloat16_rn(v.z - __bfloat162float(h2));
            __nv_bfloat16 l3 = __float2bfloat16_rn(v.w - __bfloat162float(h3));
            uint32_t off = (uint32_t)r * 256u + (((uint32_t)q * 8u) ^ (((uint32_t)r & 7u) * 16u));
            __nv_bfloat162 ph0{h0, h1}, ph1{h2, h3}, pl0{l0, l1}, pl1{l2, l3};
            uint2 uh{*(uint32_t*)&ph0, *(uint32_t*)&ph1};
            uint2 ul{*(uint32_t*)&pl0, *(uint32_t*)&pl1};
            *(uint2*)(smem + SM_AHI + off) = uh;
            *(uint2*)(smem + SM_ALO + off) = ul;
        }
    }
    __syncthreads();

    int g = lane >> 3, i8 = lane & 7;
    int rA = i8 + 8 * (g & 1);
    int rB = i8 + 8 * (g >> 1);
    int wm = (wid & 3) * 32;
    int wc = wid >> 2;
    bool isW2 = wc >= 2;
    int wn = (wc & 1) * 64;
    uint32_t aHI = sbase + SM_AHI, aLO = sbase + SM_ALO;
    uint32_t wH = sbase + SM_W + (isW2 ? 2 : 0) * 32768;
    uint32_t wL = wH + 32768;
    uint32_t swzA = (uint32_t)i8 * 16u;

    float c[2][8][4];
#pragma unroll
    for (int mi = 0; mi < 2; mi++)
#pragma unroll
        for (int ni = 0; ni < 8; ni++)
#pragma unroll
            for (int q = 0; q < 4; q++) c[mi][ni][q] = 0.f;

#pragma unroll
    for (int ks = 0; ks < 8; ks++) {
        uint32_t kA = ((uint32_t)(ks * 32 + (g >> 1) * 16)) ^ swzA;
        uint32_t kB = ((uint32_t)(ks * 32 + (g & 1) * 16)) ^ swzA;
        uint32_t bh[8][2], bl[8][2];
#pragma unroll
        for (int nt = 0; nt < 4; nt++) {
            uint32_t rowoff = (uint32_t)(wn + nt * 16 + rB) * 256u;
            ldsm4(bh[nt * 2][0], bh[nt * 2][1], bh[nt * 2 + 1][0], bh[nt * 2 + 1][1],
                  wH + rowoff + kB);
            ldsm4(bl[nt * 2][0], bl[nt * 2][1], bl[nt * 2 + 1][0], bl[nt * 2 + 1][1],
                  wL + rowoff + kB);
        }
        uint32_t a[2][4];
#pragma unroll
        for (int mi = 0; mi < 2; mi++)
            ldsm4(a[mi][0], a[mi][1], a[mi][2], a[mi][3],
                  aHI + (uint32_t)(wm + mi * 16 + rA) * 256u + kA);
#pragma unroll
        for (int mi = 0; mi < 2; mi++)
#pragma unroll
            for (int ni = 0; ni < 8; ni++) {
                mma16816(c[mi][ni], a[mi], bh[ni]);
                mma16816(c[mi][ni], a[mi], bl[ni]);
            }
#pragma unroll
        for (int mi = 0; mi < 2; mi++)
            ldsm4(a[mi][0], a[mi][1], a[mi][2], a[mi][3],
                  aLO + (uint32_t)(wm + mi * 16 + rA) * 256u + kA);
#pragma unroll
        for (int mi = 0; mi < 2; mi++)
#pragma unroll
            for (int ni = 0; ni < 8; ni++)
                mma16816(c[mi][ni], a[mi], bh[ni]);
    }

    int groupr = lane >> 2, qc = lane & 3;
#pragma unroll
    for (int mi = 0; mi < 2; mi++) {
        int r1 = wm + mi * 16 + groupr, r2 = r1 + 8;
        int gr1 = row0 + r1, gr2 = row0 + r2;
        float rv1 = sdeg[r1], rv2 = sdeg[r2];
#pragma unroll
        for (int ni = 0; ni < 8; ni++) {
            int cc = wn + ni * 8 + qc * 2;
            float* acc = c[mi][ni];
            if (!isW2) {
                float2 v1{acc[0] + sbias[cc], acc[1] + sbias[cc + 1]};
                float2 v2{acc[2] + sbias[cc], acc[3] + sbias[cc + 1]};
                if (gr1 < N_NODES) *(float2*)&out[(size_t)gr1 * D + cc] = v1;
                if (gr2 < N_NODES) *(float2*)&out[(size_t)gr2 * D + cc] = v2;
            } else {
                float2 v1{(acc[0] + sbias[D + cc]) * rv1,
                          (acc[1] + sbias[D + cc + 1]) * rv1};
                float2 v2{(acc[2] + sbias[D + cc]) * rv2,
                          (acc[3] + sbias[D + cc + 1]) * rv2};
                if (gr1 < N_NODES) *(float2*)&g_conv[(size_t)gr1 * D + cc] = v1;
                if (gr2 < N_NODES) *(float2*)&g_conv[(size_t)gr2 * D + cc] = v2;
            }
        }
    }
}

// ---------------- fused aggregate + finalize --------------------------------
// warp per node (8 nodes/warp): agg = sum conv[s]; h = relu(h1 + agg*rr) + nodes
// also accumulates column sum of h into g_an.
#define ANB 64                       // nodes per block (8 warps x 8 nodes)
__global__ __launch_bounds__(256)
void aggregate_kernel(const float* __restrict__ nodes,
                      float* __restrict__ out) {
    __shared__ float scol[D];
    int tid = threadIdx.x, w = tid >> 5, lane = tid & 31;
    if (tid < D) scol[tid] = 0.f;
    __syncthreads();

    float4 col = make_float4(0.f, 0.f, 0.f, 0.f);
#pragma unroll 1
    for (int j = 0; j < 8; j++) {
        int node = blockIdx.x * ANB + w * 8 + j;
        if (node >= N_NODES) break;
        int e0 = g_rowstart[node], e1 = g_rowstart[node + 1];
        float4 acc = make_float4(0.f, 0.f, 0.f, 0.f);
        for (int e = e0; e < e1; e++) {
            int s = g_csr[e];
            float4 v = *(const float4*)&g_conv[(size_t)s * D + lane * 4];
            acc.x += v.x; acc.y += v.y; acc.z += v.z; acc.w += v.w;
        }
        float rr = g_degr[node];
        size_t idx = (size_t)node * D + lane * 4;
        float4 h1 = *(const float4*)&out[idx];
        float4 nd = *(const float4*)&nodes[idx];
        float4 h;
        h.x = fmaxf(h1.x + acc.x * rr, 0.f) + nd.x;
        h.y = fmaxf(h1.y + acc.y * rr, 0.f) + nd.y;
        h.z = fmaxf(h1.z + acc.z * rr, 0.f) + nd.z;
        h.w = fmaxf(h1.w + acc.w * rr, 0.f) + nd.w;
        *(float4*)&out[idx] = h;
        col.x += h.x; col.y += h.y; col.z += h.z; col.w += h.w;
    }
    atomicAdd(&scol[lane * 4 + 0], col.x);
    atomicAdd(&scol[lane * 4 + 1], col.y);
    atomicAdd(&scol[lane * 4 + 2], col.z);
    atomicAdd(&scol[lane * 4 + 3], col.w);
    __syncthreads();
    if (tid < D) atomicAdd(&g_an[tid], scol[tid]);
}

// ---------------- global update: g_new = g + relu([an; g] @ Wg + bg) -------
__global__ void gnew_kernel(const float* __restrict__ g,
                            const float* __restrict__ Wg,
                            const float* __restrict__ bg,
                            float* __restrict__ out2) {
    __shared__ float sv[2 * D];
    int c = threadIdx.x;
    sv[c] = g_an[c];
    sv[D + c] = g[c];
    __syncthreads();
    float acc = bg[c];
#pragma unroll 8
    for (int k = 0; k < 2 * D; k++) acc += sv[k] * Wg[k * D + c];
    out2[c] = g[c] + fmaxf(acc, 0.f);
}

// ---------------- launch ----------------------------------------------------
extern "C" void kernel_launch(void* const* d_in, const int* in_sizes, int n_in,
                              void* d_out, int out_size) {
    const float* nodes    = (const float*)d_in[0];
    const float* globals_ = (const float*)d_in[1];
    const int*   senders   = (const int*)d_in[2];
    const int*   receivers = (const int*)d_in[3];
    const float* W1w = (const float*)d_in[4];
    const float* W1b = (const float*)d_in[5];
    const float* W2w = (const float*)d_in[6];
    const float* W2b = (const float*)d_in[7];
    const float* W3w = (const float*)d_in[8];
    const float* W3b = (const float*)d_in[9];
    const float* Wgw = (const float*)d_in[10];
    const float* Wgb = (const float*)d_in[11];
    float* out = (float*)d_out;

    cudaFuncSetAttribute(gemm_hmma_kernel, cudaFuncAttributeMaxDynamicSharedMemorySize,
                         SM_TOTAL);

    zero_kernel<<<(N_NODES + 255) / 256, 256>>>();
    degree_kernel<<<(N_EDGES + 255) / 256, 256>>>(senders, receivers);
    rs_kernel<<<(N_NODES + 255) / 256, 256>>>();
    scan1_kernel<<<SCAN_B, 1024>>>();
    scan2_kernel<<<1, 128>>>();
    scan3_kernel<<<SCAN_B, 1024>>>();
    bucket_kernel<<<(N_EDGES + 255) / 256, 256>>>(senders, receivers);
    wprep_kernel<<<128, 256>>>(W1w, W2w);
    gvec_kernel<<<D / 4, 128>>>(globals_, W3w, W3b, W1b);
    gemm_hmma_kernel<<<NTILES, GT, SM_TOTAL>>>(nodes, W2b, out);
    aggregate_kernel<<<(N_NODES + ANB - 1) / ANB, 256>>>(nodes, out);
    gnew_kernel<<<1, 128>>>(globals_, Wgw, Wgb, out + (size_t)N_NODES * D);
}

// round 11
// speedup vs baseline: 2.0643x; 1.0596x over previous
#include <cuda_runtime.h>
#include <cuda_bf16.h>
#include <cstdint>

#define N_NODES 100000
#define N_EDGES 640000
#define D 128
#define TILE_M 128
#define CTA_M 256                       // two stages of TILE_M per CTA
#define NTILES2 ((N_NODES + CTA_M - 1) / CTA_M)
#define SCAN_B 98                       // ceil(100000/1024)

// ---------------- scratch (device globals; no dynamic allocation) ----------
__device__ float g_conv[N_NODES * D];   // (nodes@W2 + b2) * rsqrt(send_deg)
__device__ float g_gvec[D];             // globals@W3 + b3 + b1  (folded)
__device__ float g_an[D];               // column sum of h
__device__ int   g_cnt_s[N_NODES];      // send degree (int)
__device__ int   g_cnt_r[N_NODES];      // recv degree (int)
__device__ int   g_rowstart[N_NODES + 1];
__device__ int   g_cursor[N_NODES];
__device__ int   g_bsum[128], g_bscan[128];
__device__ int   g_csr[N_EDGES];        // sender ids bucketed by receiver
// weight images, transposed to [n][k], bf16 hi/lo, XOR-swizzled: W1h,W1l,W2h,W2l
__device__ __align__(16) unsigned char g_Wimg[4 * 32768];

// swizzled byte offset of element (row, k) in a 128x128 bf16 image (256B rows)
__device__ __forceinline__ uint32_t swz_off(int row, int k) {
    return (uint32_t)row * 256u + (((uint32_t)k * 2u) ^ (((uint32_t)row & 7u) * 16u));
}
__device__ __forceinline__ uint32_t smem_u32(const void* p) {
    uint32_t a;
    asm("{ .reg .u64 t; cvta.to.shared.u64 t, %1; cvt.u32.u64 %0, t; }" : "=r"(a) : "l"(p));
    return a;
}
__device__ __forceinline__ void ldsm4(uint32_t& r0, uint32_t& r1, uint32_t& r2,
                                      uint32_t& r3, uint32_t addr) {
    asm volatile("ldmatrix.sync.aligned.m8n8.x4.shared.b16 {%0,%1,%2,%3}, [%4];"
                 : "=r"(r0), "=r"(r1), "=r"(r2), "=r"(r3) : "r"(addr));
}
__device__ __forceinline__ void mma16816(float* c, const uint32_t* a,
                                         const uint32_t* b) {
    asm volatile(
        "mma.sync.aligned.m16n8k16.row.col.f32.bf16.bf16.f32 "
        "{%0,%1,%2,%3}, {%4,%5,%6,%7}, {%8,%9}, {%0,%1,%2,%3};"
        : "+f"(c[0]), "+f"(c[1]), "+f"(c[2]), "+f"(c[3])
        : "r"(a[0]), "r"(a[1]), "r"(a[2]), "r"(a[3]), "r"(b[0]), "r"(b[1]));
}

// ---------------- init / degrees -------------------------------------------
__global__ void zero_kernel() {
    int i = blockIdx.x * blockDim.x + threadIdx.x;
    if (i < N_NODES) { g_cnt_s[i] = 0; g_cnt_r[i] = 0; }
}
__global__ void degree_kernel(const int* __restrict__ senders,
                              const int* __restrict__ receivers) {
    int e = blockIdx.x * blockDim.x + threadIdx.x;
    if (e < N_EDGES) {
        atomicAdd(&g_cnt_s[senders[e]], 1);
        atomicAdd(&g_cnt_r[receivers[e]], 1);
    }
}

// ---------------- exclusive scan of recv counts -> g_rowstart ---------------
__global__ __launch_bounds__(1024) void scan1_kernel() {
    __shared__ int wsum[32];
    int t = threadIdx.x, i = blockIdx.x * 1024 + t;
    int lane = t & 31, w = t >> 5;
    int v = (i < N_NODES) ? g_cnt_r[i] : 0;
    int x = v;
#pragma unroll
    for (int off = 1; off < 32; off <<= 1) {
        int y = __shfl_up_sync(0xffffffffu, x, off);
        if (lane >= off) x += y;
    }
    if (lane == 31) wsum[w] = x;
    __syncthreads();
    if (w == 0) {
        int s = wsum[lane];
#pragma unroll
        for (int off = 1; off < 32; off <<= 1) {
            int y = __shfl_up_sync(0xffffffffu, s, off);
            if (lane >= off) s += y;
        }
        wsum[lane] = s;
    }
    __syncthreads();
    int incl = x + (w > 0 ? wsum[w - 1] : 0);
    if (i < N_NODES) g_rowstart[i] = incl - v;
    if (t == 1023) g_bsum[blockIdx.x] = incl;
}
__global__ void scan2_kernel() {          // 1 block, 128 threads
    __shared__ int tmp[128];
    int t = threadIdx.x;
    int v = (t < SCAN_B) ? g_bsum[t] : 0;
    tmp[t] = v;
    __syncthreads();
#pragma unroll
    for (int off = 1; off < 128; off <<= 1) {
        int x = (t >= off) ? tmp[t - off] : 0;
        __syncthreads();
        tmp[t] += x;
        __syncthreads();
    }
    g_bscan[t] = tmp[t] - v;              // exclusive
}
__global__ __launch_bounds__(1024) void scan3_kernel() {
    int t = threadIdx.x, i = blockIdx.x * 1024 + t;
    if (i < N_NODES) {
        int v = g_rowstart[i] + g_bscan[blockIdx.x];
        g_rowstart[i] = v;
        g_cursor[i] = v;
    }
    if (i == N_NODES) g_rowstart[N_NODES] = N_EDGES;
}
__global__ void bucket_kernel(const int* __restrict__ senders,
                              const int* __restrict__ receivers) {
    int e = blockIdx.x * blockDim.x + threadIdx.x;
    if (e < N_EDGES) {
        int pos = atomicAdd(&g_cursor[receivers[e]], 1);
        g_csr[pos] = senders[e];
    }
}

// ---------------- fused wprep + gvec + an-zero ------------------------------
// blocks 0..127: weight split/transpose. blocks 128..143: gvec (8 warps = 8 cols)
__global__ __launch_bounds__(256)
void prep_kernel(const float* __restrict__ W1, const float* __restrict__ W2,
                 const float* __restrict__ g,  const float* __restrict__ W3,
                 const float* __restrict__ b3, const float* __restrict__ b1) {
    int bx = blockIdx.x, tid = threadIdx.x;
    if (bx < 128) {
        int mat = bx & 1;                     // 0: W1, 1: W2
        int idx = (bx >> 1) * 256 + tid;      // 0..16383
        const float* W = mat ? W2 : W1;
        unsigned char* hi = g_Wimg + (size_t)(mat * 2) * 32768;
        unsigned char* lo = hi + 32768;
        int k = idx >> 7, n = idx & 127;      // coalesced read of W[k][n]
        float w = W[k * D + n];
        __nv_bfloat16 h = __float2bfloat16_rn(w);
        __nv_bfloat16 l = __float2bfloat16_rn(w - __bfloat162float(h));
        uint32_t off = swz_off(n, k);
        *(__nv_bfloat16*)(hi + off) = h;
        *(__nv_bfloat16*)(lo + off) = l;
    } else {
        if (bx == 128 && tid < D) g_an[tid] = 0.f;
        int w = tid >> 5, lane = tid & 31;
        int c = (bx - 128) * 8 + w;
        float s = 0.f;
#pragma unroll
        for (int k = lane; k < D; k += 32) s += g[k] * W3[k * D + c];
#pragma unroll
        for (int o = 16; o; o >>= 1) s += __shfl_xor_sync(0xffffffffu, s, o);
        if (lane == 0) g_gvec[c] = s + b3[c] + b1[c];
    }
}

// ---------------- HMMA dual GEMM (512 threads, 16 warps, 2 row-tiles) -------
#define SM_AHI  0
#define SM_ALO  32768
#define SM_W    65536                       // W1h,W1l,W2h,W2l (131072 B)
#define SM_BIAS (SM_W + 4 * 32768)          // 256 floats: gvec | b2
#define SM_DEG  (SM_BIAS + 1024)            // 256 floats (rsqrt send deg)
#define SM_TOTAL (SM_DEG + 1024)
#define GT 512

__global__ __launch_bounds__(GT, 1)
void gemm_hmma_kernel(const float* __restrict__ nodes,
                      const float* __restrict__ b2,
                      float* __restrict__ out) {
    extern __shared__ unsigned char smem[];
    uint32_t sbase = smem_u32(smem);
    int tid = threadIdx.x, wid = tid >> 5, lane = tid & 31;
    int row0 = blockIdx.x * CTA_M;
    float* sbias = (float*)(smem + SM_BIAS);
    float* sdeg  = (float*)(smem + SM_DEG);

    // ---- once-per-CTA prologue: biases, degs, weight images ---------------
    if (tid < D) {
        sbias[tid] = g_gvec[tid];
        sbias[D + tid] = b2[tid];
    }
    if (tid < CTA_M) {
        int gr = row0 + tid;
        sdeg[tid] = (gr < N_NODES) ? rsqrtf(fmaxf((float)g_cnt_s[gr], 1.f)) : 0.f;
    }
    {
        const float4* src = (const float4*)g_Wimg;
        float4* dst = (float4*)(smem + SM_W);
#pragma unroll
        for (int i = tid; i < (4 * 32768) / 16; i += GT) dst[i] = src[i];
    }

    // warp-constant addressing (identical math to the r9 passing kernel)
    int g = lane >> 3, i8 = lane & 7;
    int rA = i8 + 8 * (g & 1);
    int rB = i8 + 8 * (g >> 1);
    int wm = (wid & 3) * 32;
    int wc = wid >> 2;
    bool isW2 = wc >= 2;
    int wn = (wc & 1) * 64;
    uint32_t aHI = sbase + SM_AHI, aLO = sbase + SM_ALO;
    uint32_t wH = sbase + SM_W + (isW2 ? 2 : 0) * 32768;
    uint32_t wL = wH + 32768;
    uint32_t swzA = (uint32_t)i8 * 16u;
    int groupr = lane >> 2, qc = lane & 3;

#pragma unroll 1
    for (int st = 0; st < 2; st++) {
        int rbase = row0 + st * TILE_M;
        if (rbase >= N_NODES) break;
        // ---- stage A convert: fp32 -> bf16 hi/lo, swizzled ----------------
        {
            const float4* n4 = (const float4*)nodes;
#pragma unroll
            for (int i = tid; i < TILE_M * (D / 4); i += GT) {
                int r = i >> 5, q = i & 31;
                int gr = rbase + r;
                float4 v = (gr < N_NODES) ? n4[(size_t)gr * (D / 4) + q]
                                          : make_float4(0.f, 0.f, 0.f, 0.f);
                __nv_bfloat16 h0 = __float2bfloat16_rn(v.x), h1 = __float2bfloat16_rn(v.y);
                __nv_bfloat16 h2 = __float2bfloat16_rn(v.z), h3 = __float2bfloat16_rn(v.w);
                __nv_bfloat16 l0 = __float2bfloat16_rn(v.x - __bfloat162float(h0));
                __nv_bfloat16 l1 = __float2bfloat16_rn(v.y - __bfloat162float(h1));
                __nv_bfloat16 l2 = __float2bfloat16_rn(v.z - __bfloat162float(h2));
                __nv_bfloat16 l3 = __float2bfloat16_rn(v.w - __bfloat162float(h3));
                uint32_t off = (uint32_t)r * 256u +
                               (((uint32_t)q * 8u) ^ (((uint32_t)r & 7u) * 16u));
                __nv_bfloat162 ph0{h0, h1}, ph1{h2, h3}, pl0{l0, l1}, pl1{l2, l3};
                uint2 uh{*(uint32_t*)&ph0, *(uint32_t*)&ph1};
                uint2 ul{*(uint32_t*)&pl0, *(uint32_t*)&pl1};
                *(uint2*)(smem + SM_AHI + off) = uh;
                *(uint2*)(smem + SM_ALO + off) = ul;
            }
        }
        __syncthreads();

        // ---- mainloop ------------------------------------------------------
        float c[2][8][4];
#pragma unroll
        for (int mi = 0; mi < 2; mi++)
#pragma unroll
            for (int ni = 0; ni < 8; ni++)
#pragma unroll
                for (int q = 0; q < 4; q++) c[mi][ni][q] = 0.f;

#pragma unroll
        for (int ks = 0; ks < 8; ks++) {
            uint32_t kA = ((uint32_t)(ks * 32 + (g >> 1) * 16)) ^ swzA;
            uint32_t kB = ((uint32_t)(ks * 32 + (g & 1) * 16)) ^ swzA;
            uint32_t bh[8][2], bl[8][2];
#pragma unroll
            for (int nt = 0; nt < 4; nt++) {
                uint32_t rowoff = (uint32_t)(wn + nt * 16 + rB) * 256u;
                ldsm4(bh[nt * 2][0], bh[nt * 2][1], bh[nt * 2 + 1][0], bh[nt * 2 + 1][1],
                      wH + rowoff + kB);
                ldsm4(bl[nt * 2][0], bl[nt * 2][1], bl[nt * 2 + 1][0], bl[nt * 2 + 1][1],
                      wL + rowoff + kB);
            }
            uint32_t a[2][4];
#pragma unroll
            for (int mi = 0; mi < 2; mi++)
                ldsm4(a[mi][0], a[mi][1], a[mi][2], a[mi][3],
                      aHI + (uint32_t)(wm + mi * 16 + rA) * 256u + kA);
#pragma unroll
            for (int mi = 0; mi < 2; mi++)
#pragma unroll
                for (int ni = 0; ni < 8; ni++) {
                    mma16816(c[mi][ni], a[mi], bh[ni]);
                    mma16816(c[mi][ni], a[mi], bl[ni]);
                }
#pragma unroll
            for (int mi = 0; mi < 2; mi++)
                ldsm4(a[mi][0], a[mi][1], a[mi][2], a[mi][3],
                      aLO + (uint32_t)(wm + mi * 16 + rA) * 256u + kA);
#pragma unroll
            for (int mi = 0; mi < 2; mi++)
#pragma unroll
                for (int ni = 0; ni < 8; ni++)
                    mma16816(c[mi][ni], a[mi], bh[ni]);
        }

        // ---- stage epilogue ------------------------------------------------
#pragma unroll
        for (int mi = 0; mi < 2; mi++) {
            int r1 = wm + mi * 16 + groupr, r2 = r1 + 8;
            int gr1 = rbase + r1, gr2 = rbase + r2;
            float rv1 = sdeg[st * TILE_M + r1], rv2 = sdeg[st * TILE_M + r2];
#pragma unroll
            for (int ni = 0; ni < 8; ni++) {
                int cc = wn + ni * 8 + qc * 2;
                float* acc = c[mi][ni];
                if (!isW2) {
                    float2 v1{acc[0] + sbias[cc], acc[1] + sbias[cc + 1]};
                    float2 v2{acc[2] + sbias[cc], acc[3] + sbias[cc + 1]};
                    if (gr1 < N_NODES) *(float2*)&out[(size_t)gr1 * D + cc] = v1;
                    if (gr2 < N_NODES) *(float2*)&out[(size_t)gr2 * D + cc] = v2;
                } else {
                    float2 v1{(acc[0] + sbias[D + cc]) * rv1,
                              (acc[1] + sbias[D + cc + 1]) * rv1};
                    float2 v2{(acc[2] + sbias[D + cc]) * rv2,
                              (acc[3] + sbias[D + cc + 1]) * rv2};
                    if (gr1 < N_NODES) *(float2*)&g_conv[(size_t)gr1 * D + cc] = v1;
                    if (gr2 < N_NODES) *(float2*)&g_conv[(size_t)gr2 * D + cc] = v2;
                }
            }
        }
        __syncthreads();   // A smem reused next stage
    }
}

// ---------------- fused aggregate + finalize --------------------------------
// warp per node (8 nodes/warp): agg = sum conv[s]; h = relu(h1 + agg*rr) + nodes
// also accumulates column sum of h into g_an.
#define ANB 64                       // nodes per block (8 warps x 8 nodes)
__global__ __launch_bounds__(256)
void aggregate_kernel(const float* __restrict__ nodes,
                      float* __restrict__ out) {
    __shared__ float scol[D];
    int tid = threadIdx.x, w = tid >> 5, lane = tid & 31;
    if (tid < D) scol[tid] = 0.f;
    __syncthreads();

    float4 col = make_float4(0.f, 0.f, 0.f, 0.f);
#pragma unroll 1
    for (int j = 0; j < 8; j++) {
        int node = blockIdx.x * ANB + w * 8 + j;
        if (node >= N_NODES) break;
        int e0 = g_rowstart[node], e1 = g_rowstart[node + 1];
        float4 acc0 = make_float4(0.f, 0.f, 0.f, 0.f);
        float4 acc1 = make_float4(0.f, 0.f, 0.f, 0.f);
        int e = e0;
        for (; e + 1 < e1; e += 2) {
            int s0 = __ldg(&g_csr[e]);
            int s1 = __ldg(&g_csr[e + 1]);
            float4 v0 = *(const float4*)&g_conv[(size_t)s0 * D + lane * 4];
            float4 v1 = *(const float4*)&g_conv[(size_t)s1 * D + lane * 4];
            acc0.x += v0.x; acc0.y += v0.y; acc0.z += v0.z; acc0.w += v0.w;
            acc1.x += v1.x; acc1.y += v1.y; acc1.z += v1.z; acc1.w += v1.w;
        }
        if (e < e1) {
            int s0 = __ldg(&g_csr[e]);
            float4 v0 = *(const float4*)&g_conv[(size_t)s0 * D + lane * 4];
            acc0.x += v0.x; acc0.y += v0.y; acc0.z += v0.z; acc0.w += v0.w;
        }
        acc0.x += acc1.x; acc0.y += acc1.y; acc0.z += acc1.z; acc0.w += acc1.w;
        float rr = rsqrtf(fmaxf((float)g_cnt_r[node], 1.f));
        size_t idx = (size_t)node * D + lane * 4;
        float4 h1 = *(const float4*)&out[idx];
        float4 nd = *(const float4*)&nodes[idx];
        float4 h;
        h.x = fmaxf(h1.x + acc0.x * rr, 0.f) + nd.x;
        h.y = fmaxf(h1.y + acc0.y * rr, 0.f) + nd.y;
        h.z = fmaxf(h1.z + acc0.z * rr, 0.f) + nd.z;
        h.w = fmaxf(h1.w + acc0.w * rr, 0.f) + nd.w;
        *(float4*)&out[idx] = h;
        col.x += h.x; col.y += h.y; col.z += h.z; col.w += h.w;
    }
    atomicAdd(&scol[lane * 4 + 0], col.x);
    atomicAdd(&scol[lane * 4 + 1], col.y);
    atomicAdd(&scol[lane * 4 + 2], col.z);
    atomicAdd(&scol[lane * 4 + 3], col.w);
    __syncthreads();
    if (tid < D) atomicAdd(&g_an[tid], scol[tid]);
}

// ---------------- global update: g_new = g + relu([an; g] @ Wg + bg) -------
__global__ void gnew_kernel(const float* __restrict__ g,
                            const float* __restrict__ Wg,
                            const float* __restrict__ bg,
                            float* __restrict__ out2) {
    __shared__ float sv[2 * D];
    int c = threadIdx.x;
    sv[c] = g_an[c];
    sv[D + c] = g[c];
    __syncthreads();
    float acc = bg[c];
#pragma unroll 8
    for (int k = 0; k < 2 * D; k++) acc += sv[k] * Wg[k * D + c];
    out2[c] = g[c] + fmaxf(acc, 0.f);
}

// ---------------- launch ----------------------------------------------------
extern "C" void kernel_launch(void* const* d_in, const int* in_sizes, int n_in,
                              void* d_out, int out_size) {
    const float* nodes    = (const float*)d_in[0];
    const float* globals_ = (const float*)d_in[1];
    const int*   senders   = (const int*)d_in[2];
    const int*   receivers = (const int*)d_in[3];
    const float* W1w = (const float*)d_in[4];
    const float* W1b = (const float*)d_in[5];
    const float* W2w = (const float*)d_in[6];
    const float* W2b = (const float*)d_in[7];
    const float* W3w = (const float*)d_in[8];
    const float* W3b = (const float*)d_in[9];
    const float* Wgw = (const float*)d_in[10];
    const float* Wgb = (const float*)d_in[11];
    float* out = (float*)d_out;

    cudaFuncSetAttribute(gemm_hmma_kernel, cudaFuncAttributeMaxDynamicSharedMemorySize,
                         SM_TOTAL);

    zero_kernel<<<(N_NODES + 255) / 256, 256>>>();
    degree_kernel<<<(N_EDGES + 255) / 256, 256>>>(senders, receivers);
    scan1_kernel<<<SCAN_B, 1024>>>();
    scan2_kernel<<<1, 128>>>();
    scan3_kernel<<<SCAN_B, 1024>>>();
    bucket_kernel<<<(N_EDGES + 255) / 256, 256>>>(senders, receivers);
    prep_kernel<<<144, 256>>>(W1w, W2w, globals_, W3w, W3b, W1b);
    gemm_hmma_kernel<<<NTILES2, GT, SM_TOTAL>>>(nodes, W2b, out);
    aggregate_kernel<<<(N_NODES + ANB - 1) / ANB, 256>>>(nodes, out);
    gnew_kernel<<<1, 128>>>(globals_, Wgw, Wgb, out + (size_t)N_NODES * D);
}